// round 7
// baseline (speedup 1.0000x reference)
#include <cuda_runtime.h>
#include <cuda_bf16.h>

#define NN    65536
#define NGR   32768
#define HH    64
#define BB    64
#define MAXD  10
#define ECAP  3145728   // EG + ES + 2*EX

// ---- scratch: device globals (no allocation allowed) ----
__device__ __align__(16) float g_h [(size_t)NN * HH];   // ping
__device__ __align__(16) float g_h2[(size_t)NN * HH];   // pong
__device__ int   g_esrc[ECAP];            // dst-bucketed src lists, 4 segments
__device__ int   g_cnt[4][NGR];           // per-conv-type receive degree
__device__ int   g_off[4][NGR];           // exclusive offsets
__device__ int   g_cur[4][NGR];           // fill cursors
__device__ float g_pooled[BB * HH];

// ---------------- zero counters + pooled ----------------
__global__ void zero_kernel() {
    int gid = blockIdx.x * blockDim.x + threadIdx.x;
    if (gid < 4 * NGR) ((int*)g_cnt)[gid] = 0;
    else if (gid < 4 * NGR + BB * HH) g_pooled[gid - 4 * NGR] = 0.f;
}

// ---------------- CSR build: count ----------------
__global__ void count_kernel(const int* __restrict__ ei, int E, int t, int base) {
    int e = blockIdx.x * blockDim.x + threadIdx.x;
    if (e >= E) return;
    int dst = __ldg(ei + E + e);
    atomicAdd(&g_cnt[t][dst - base], 1);
}

// ---------------- CSR build: exclusive scan of 32768 counts (1 block) ----------------
__global__ void scan_kernel(int t) {
    __shared__ int part[1024];
    int tid = threadIdx.x;
    int s = 0;
#pragma unroll 8
    for (int i = 0; i < 32; i++) s += g_cnt[t][tid * 32 + i];
    part[tid] = s;
    __syncthreads();
    for (int d = 1; d < 1024; d <<= 1) {
        int v = (tid >= d) ? part[tid - d] : 0;
        __syncthreads();
        part[tid] += v;
        __syncthreads();
    }
    int run = (tid == 0) ? 0 : part[tid - 1];
#pragma unroll 8
    for (int i = 0; i < 32; i++) {
        g_off[t][tid * 32 + i] = run;
        g_cur[t][tid * 32 + i] = run;
        run += g_cnt[t][tid * 32 + i];
    }
}

// ---------------- CSR build: fill buckets ----------------
__global__ void fill_kernel(const int* __restrict__ ei, int E, int t, int base, int seg) {
    int e = blockIdx.x * blockDim.x + threadIdx.x;
    if (e >= E) return;
    int src = __ldg(ei + e);
    int dst = __ldg(ei + E + e);
    int slot = atomicAdd(&g_cur[t][dst - base], 1);
    g_esrc[seg + slot] = src;
}

// ---------------- embed: h = x @ W(32x64) + b ----------------
__global__ void embed_kernel(const float* __restrict__ x,
                             const float* __restrict__ W,
                             const float* __restrict__ b) {
    int node = blockIdx.x * 8 + (threadIdx.x >> 5);
    int lane = threadIdx.x & 31;
    float xv = x[(size_t)node * 32 + lane];
    int c = lane * 2;
    float2 acc = make_float2(b[c], b[c + 1]);
#pragma unroll 8
    for (int k = 0; k < 32; k++) {
        float xk = __shfl_sync(0xffffffffu, xv, k);
        float2 w = *(const float2*)(W + k * 64 + c);
        acc.x += xk * w.x;
        acc.y += xk * w.y;
    }
    *(float2*)(g_h + (size_t)node * 64 + c) = acc;
}

// ---------------- relu (in place on current buffer) ----------------
__global__ void relu_kernel(int flip) {
    float* buf = flip ? g_h2 : g_h;
    int gid = blockIdx.x * blockDim.x + threadIdx.x;   // N*H/4 quads
    float4* p = ((float4*)buf) + gid;
    float4 v = *p;
    v.x = fmaxf(v.x, 0.f); v.y = fmaxf(v.y, 0.f);
    v.z = fmaxf(v.z, 0.f); v.w = fmaxf(v.w, 0.f);
    *p = v;
}

// ---------------- fused gather + MFConv transform (warp per node) ----------------
__global__ void conv_kernel(int flip, int t, int base, int seg,
                            const float* __restrict__ Wl,
                            const float* __restrict__ bl,
                            const float* __restrict__ Wr) {
    const float* __restrict__ in = flip ? g_h2 : g_h;
    float* __restrict__ out      = flip ? g_h  : g_h2;
    int node = blockIdx.x * 8 + (threadIdx.x >> 5);
    int lane = threadIdx.x & 31;
    size_t off = (size_t)node * 64;
    int li = node - base;
    int n = (li >= 0 && li < NGR) ? g_cnt[t][li] : 0;
    if (n == 0) {   // not a target of this conv, or lone node: carry features
        float2 v = *(const float2*)(in + off + lane * 2);
        *(float2*)(out + off + lane * 2) = v;
        return;
    }
    const int* ep = g_esrc + seg + g_off[t][li];
    float a_lo = 0.f, a_hi = 0.f;
    int e = 0;
    for (; e + 4 <= n; e += 4) {
        int s0 = __ldg(ep + e), s1 = __ldg(ep + e + 1);
        int s2 = __ldg(ep + e + 2), s3 = __ldg(ep + e + 3);
        float v0 = in[(size_t)s0 * 64 + lane],      w0 = in[(size_t)s0 * 64 + 32 + lane];
        float v1 = in[(size_t)s1 * 64 + lane],      w1 = in[(size_t)s1 * 64 + 32 + lane];
        float v2 = in[(size_t)s2 * 64 + lane],      w2 = in[(size_t)s2 * 64 + 32 + lane];
        float v3 = in[(size_t)s3 * 64 + lane],      w3 = in[(size_t)s3 * 64 + 32 + lane];
        a_lo += (v0 + v1) + (v2 + v3);
        a_hi += (w0 + w1) + (w2 + w3);
    }
    for (; e < n; e++) {
        int s = __ldg(ep + e);
        a_lo += in[(size_t)s * 64 + lane];
        a_hi += in[(size_t)s * 64 + 32 + lane];
    }
    int d = n > MAXD ? MAXD : n;
    const float* wl = Wl + (size_t)d * 4096;
    const float* wr = Wr + (size_t)d * 4096;
    float h_lo = in[off + lane];
    float h_hi = in[off + 32 + lane];
    int c = lane * 2;
    float2 acc = *(const float2*)(bl + (size_t)d * 64 + c);
#pragma unroll 8
    for (int k = 0; k < 32; k++) {
        float ak = __shfl_sync(0xffffffffu, a_lo, k);
        float hk = __shfl_sync(0xffffffffu, h_lo, k);
        float2 wlk = *(const float2*)(wl + k * 64 + c);
        float2 wrk = *(const float2*)(wr + k * 64 + c);
        acc.x += ak * wlk.x + hk * wrk.x;
        acc.y += ak * wlk.y + hk * wrk.y;
    }
#pragma unroll 8
    for (int k = 0; k < 32; k++) {
        float ak = __shfl_sync(0xffffffffu, a_hi, k);
        float hk = __shfl_sync(0xffffffffu, h_hi, k);
        float2 wlk = *(const float2*)(wl + (k + 32) * 64 + c);
        float2 wrk = *(const float2*)(wr + (k + 32) * 64 + c);
        acc.x += ak * wlk.x + hk * wrk.x;
        acc.y += ak * wlk.y + hk * wrk.y;
    }
    *(float2*)(out + off + c) = acc;
}

// ---------------- pool over ground nodes (scalar f32 atomics only) ----------------
__global__ void pool_kernel(const int* __restrict__ batch_idx, int flip) {
    const float* buf = flip ? g_h2 : g_h;
    int gid = blockIdx.x * blockDim.x + threadIdx.x;  // NG*64
    int i  = gid >> 6;
    int cc = gid & 63;
    int b = __ldg(batch_idx + i);
    atomicAdd(&g_pooled[b * 64 + cc], buf[(size_t)i * 64 + cc]);
}

// ---------------- head: out = relu(pooled@W1+b1) @ W2 + b2 ----------------
__global__ void head_kernel(const float* __restrict__ W1, const float* __restrict__ b1,
                            const float* __restrict__ W2, const float* __restrict__ b2,
                            float* __restrict__ out) {
    int bidx = blockIdx.x;          // 64 blocks
    int c = threadIdx.x;            // 64 threads
    float acc = b1[c];
#pragma unroll 8
    for (int k = 0; k < 64; k++)
        acc += g_pooled[bidx * 64 + k] * W1[k * 64 + c];
    acc = fmaxf(acc, 0.f) * W2[c];
#pragma unroll
    for (int o = 16; o > 0; o >>= 1)
        acc += __shfl_down_sync(0xffffffffu, acc, o);
    __shared__ float s[2];
    if ((threadIdx.x & 31) == 0) s[threadIdx.x >> 5] = acc;
    __syncthreads();
    if (threadIdx.x == 0) out[bidx] = s[0] + s[1] + b2[0];
}

extern "C" void kernel_launch(void* const* d_in, const int* in_sizes, int n_in,
                              void* d_out, int out_size) {
    const float* x          = (const float*)d_in[0];
    const int*   edge_index = (const int*)d_in[1];   // JAX default x64-disabled -> int32
    const int*   sub_ei     = (const int*)d_in[2];
    const int*   ns_ei      = (const int*)d_in[3];
    const int*   sn_ei      = (const int*)d_in[4];
    const int*   batch_idx  = (const int*)d_in[7];
    const float* embed_W = (const float*)d_in[8];
    const float* embed_b = (const float*)d_in[9];
    const float* Wl[4] = {(const float*)d_in[10], (const float*)d_in[13],
                          (const float*)d_in[16], (const float*)d_in[19]};
    const float* bl[4] = {(const float*)d_in[11], (const float*)d_in[14],
                          (const float*)d_in[17], (const float*)d_in[20]};
    const float* Wr[4] = {(const float*)d_in[12], (const float*)d_in[15],
                          (const float*)d_in[18], (const float*)d_in[21]};
    const float* W1 = (const float*)d_in[22];
    const float* b1 = (const float*)d_in[23];
    const float* W2 = (const float*)d_in[24];
    const float* b2 = (const float*)d_in[25];
    float* out = (float*)d_out;

    // conv order per layer: ground, g2s, sub, s2g
    const int* eis[4] = {edge_index, ns_ei, sub_ei, sn_ei};
    int Es[4]    = {in_sizes[1] / 2, in_sizes[3] / 2, in_sizes[2] / 2, in_sizes[4] / 2};
    int bases[4] = {0, NGR, NGR, 0};
    int segs[4];
    segs[0] = 0;
    for (int t = 1; t < 4; t++) segs[t] = segs[t - 1] + Es[t - 1];

    zero_kernel<<<(4 * NGR + BB * HH + 255) / 256, 256>>>();
    embed_kernel<<<NN / 8, 256>>>(x, embed_W, embed_b);

    // build CSR once (edges constant across both layers)
    for (int t = 0; t < 4; t++)
        count_kernel<<<(Es[t] + 255) / 256, 256>>>(eis[t], Es[t], t, bases[t]);
    for (int t = 0; t < 4; t++)
        scan_kernel<<<1, 1024>>>(t);
    for (int t = 0; t < 4; t++)
        fill_kernel<<<(Es[t] + 255) / 256, 256>>>(eis[t], Es[t], t, bases[t], segs[t]);

    int flip = 0;
    for (int l = 0; l < 2; l++) {
        if (l) relu_kernel<<<(NN * HH / 4) / 256, 256>>>(flip);
        for (int t = 0; t < 4; t++) {
            size_t woff = (size_t)l * (MAXD + 1) * 64 * 64;
            size_t boff = (size_t)l * (MAXD + 1) * 64;
            conv_kernel<<<NN / 8, 256>>>(flip, t, bases[t], segs[t],
                                         Wl[t] + woff, bl[t] + boff, Wr[t] + woff);
            flip ^= 1;
        }
    }

    pool_kernel<<<(NGR * 64) / 256, 256>>>(batch_idx, flip);
    head_kernel<<<BB, 64>>>(W1, b1, W2, b2, out);
}

// round 8
// speedup vs baseline: 1.6236x; 1.6236x over previous
#include <cuda_runtime.h>
#include <cuda_bf16.h>

#define NN    65536
#define NGR   32768
#define HH    64
#define BB    64
#define MAXD  10
#define BKT   128      // bucket capacity per (type,node); max real degree ~66

// ---- scratch: device globals (no allocation allowed) ----
__device__ __align__(16) float g_h [(size_t)NN * HH];   // ping
__device__ __align__(16) float g_h2[(size_t)NN * HH];   // pong
__device__ int   g_bkt[(size_t)4 * NGR * BKT];          // 64MB dst-bucketed src ids
__device__ int   g_cnt[4][NGR];                         // per-conv-type receive degree
__device__ float g_pooled[BB * HH];

// ---------------- zero counters + pooled ----------------
__global__ void zero_kernel() {
    int gid = blockIdx.x * blockDim.x + threadIdx.x;
    if (gid < 4 * NGR) ((int*)g_cnt)[gid] = 0;
    else if (gid < 4 * NGR + BB * HH) g_pooled[gid - 4 * NGR] = 0.f;
}

// ---------------- single pass: bucket all 4 edge sets ----------------
__global__ void fill_all_kernel(const int* __restrict__ e0, const int* __restrict__ e1,
                                const int* __restrict__ e2, const int* __restrict__ e3,
                                int E0, int E1, int E2, int E3) {
    int e = blockIdx.x * blockDim.x + threadIdx.x;
    const int* ei; int E, t, base;
    if (e < E0)              { ei = e0; E = E0; t = 0; base = 0;   }
    else if ((e -= E0) < E1) { ei = e1; E = E1; t = 1; base = NGR; }
    else if ((e -= E1) < E2) { ei = e2; E = E2; t = 2; base = NGR; }
    else if ((e -= E2) < E3) { ei = e3; E = E3; t = 3; base = 0;   }
    else return;
    int src = __ldg(ei + e);
    int dst = __ldg(ei + E + e);
    int li  = dst - base;
    int slot = atomicAdd(&g_cnt[t][li], 1);
    if (slot < BKT) g_bkt[((size_t)(t * NGR + li) << 7) + slot] = src;
}

// ---------------- embed: h = x @ W(32x64) + b ----------------
__global__ void embed_kernel(const float* __restrict__ x,
                             const float* __restrict__ W,
                             const float* __restrict__ b) {
    int node = blockIdx.x * 8 + (threadIdx.x >> 5);
    int lane = threadIdx.x & 31;
    float xv = x[(size_t)node * 32 + lane];
    int c = lane * 2;
    float2 acc = make_float2(b[c], b[c + 1]);
#pragma unroll 8
    for (int k = 0; k < 32; k++) {
        float xk = __shfl_sync(0xffffffffu, xv, k);
        float2 w = *(const float2*)(W + k * 64 + c);
        acc.x += xk * w.x;
        acc.y += xk * w.y;
    }
    *(float2*)(g_h + (size_t)node * 64 + c) = acc;
}

// ---------------- relu on both current halves ----------------
__global__ void relu2_kernel(float* bg, float* bs) {
    int gid = blockIdx.x * blockDim.x + threadIdx.x;   // NN*16 quads
    float* buf = (gid < NGR * 16) ? bg : bs;           // halves at natural offsets
    float4* p = ((float4*)buf) + gid;
    float4 v = *p;
    v.x = fmaxf(v.x, 0.f); v.y = fmaxf(v.y, 0.f);
    v.z = fmaxf(v.z, 0.f); v.w = fmaxf(v.w, 0.f);
    *p = v;
}

// ---- single-node conv (fallback path) ----
__device__ __forceinline__ void conv_one(const float* __restrict__ in_src,
                                         const float* __restrict__ in_dst,
                                         float* __restrict__ out,
                                         const int* __restrict__ ep, int n, int lane,
                                         size_t off,
                                         const float* __restrict__ Wl,
                                         const float* __restrict__ bl,
                                         const float* __restrict__ Wr) {
    float a_lo = 0.f, a_hi = 0.f;
    int e = 0;
    for (; e + 2 <= n; e += 2) {
        int s0 = __ldg(ep + e), s1 = __ldg(ep + e + 1);
        a_lo += in_src[(size_t)s0 * 64 + lane] + in_src[(size_t)s1 * 64 + lane];
        a_hi += in_src[(size_t)s0 * 64 + 32 + lane] + in_src[(size_t)s1 * 64 + 32 + lane];
    }
    for (; e < n; e++) {
        int s = __ldg(ep + e);
        a_lo += in_src[(size_t)s * 64 + lane];
        a_hi += in_src[(size_t)s * 64 + 32 + lane];
    }
    int d = n > MAXD ? MAXD : n;
    const float* wl = Wl + (size_t)d * 4096;
    const float* wr = Wr + (size_t)d * 4096;
    float h_lo = in_dst[off + lane];
    float h_hi = in_dst[off + 32 + lane];
    int c = lane * 2;
    float2 acc = *(const float2*)(bl + (size_t)d * 64 + c);
#pragma unroll 8
    for (int k = 0; k < 32; k++) {
        float ak = __shfl_sync(0xffffffffu, a_lo, k);
        float hk = __shfl_sync(0xffffffffu, h_lo, k);
        float2 wlk = *(const float2*)(wl + k * 64 + c);
        float2 wrk = *(const float2*)(wr + k * 64 + c);
        acc.x += ak * wlk.x + hk * wrk.x;
        acc.y += ak * wlk.y + hk * wrk.y;
    }
#pragma unroll 8
    for (int k = 0; k < 32; k++) {
        float ak = __shfl_sync(0xffffffffu, a_hi, k);
        float hk = __shfl_sync(0xffffffffu, h_hi, k);
        float2 wlk = *(const float2*)(wl + (k + 32) * 64 + c);
        float2 wrk = *(const float2*)(wr + (k + 32) * 64 + c);
        acc.x += ak * wlk.x + hk * wrk.x;
        acc.y += ak * wlk.y + hk * wrk.y;
    }
    *(float2*)(out + off + c) = acc;
}

// ---------------- fused conv: 4 nodes per warp, shared-weight fast path ----------------
__global__ void conv_kernel(const float* __restrict__ in_src,
                            const float* __restrict__ in_dst,
                            float* __restrict__ out,
                            int t, int base, int copy,
                            const float* __restrict__ Wl,
                            const float* __restrict__ bl,
                            const float* __restrict__ Wr) {
    int warp = blockIdx.x * 8 + (threadIdx.x >> 5);
    int lane = threadIdx.x & 31;
    int li0 = warp * 4;                 // 4 consecutive local nodes
    int n[4], d[4];
    const int* ep[4];
    bool allpos = true;
#pragma unroll
    for (int i = 0; i < 4; i++) {
        int nn = g_cnt[t][li0 + i];
        if (nn > BKT) nn = BKT;
        n[i] = nn;
        d[i] = nn > MAXD ? MAXD : nn;
        ep[i] = g_bkt + ((size_t)(t * NGR + li0 + i) << 7);
        allpos &= (nn > 0);
    }
    if (allpos && d[0] == d[1] && d[0] == d[2] && d[0] == d[3]) {
        // ---- fast path: shared degree bucket ----
        float a_lo[4] = {0, 0, 0, 0}, a_hi[4] = {0, 0, 0, 0};
        int nm = max(max(n[0], n[1]), max(n[2], n[3]));
        for (int e = 0; e < nm; e += 2) {
#pragma unroll
            for (int i = 0; i < 4; i++) {
                if (e < n[i]) {
                    int s0 = __ldg(ep[i] + e);
                    a_lo[i] += in_src[(size_t)s0 * 64 + lane];
                    a_hi[i] += in_src[(size_t)s0 * 64 + 32 + lane];
                    if (e + 1 < n[i]) {
                        int s1 = __ldg(ep[i] + e + 1);
                        a_lo[i] += in_src[(size_t)s1 * 64 + lane];
                        a_hi[i] += in_src[(size_t)s1 * 64 + 32 + lane];
                    }
                }
            }
        }
        int dd = d[0];
        const float* wl = Wl + (size_t)dd * 4096;
        const float* wr = Wr + (size_t)dd * 4096;
        int c = lane * 2;
        float2 bv = *(const float2*)(bl + (size_t)dd * 64 + c);
        float2 acc[4];
        float h_lo[4], h_hi[4];
#pragma unroll
        for (int i = 0; i < 4; i++) {
            acc[i] = bv;
            size_t off = (size_t)(base + li0 + i) * 64;
            h_lo[i] = in_dst[off + lane];
            h_hi[i] = in_dst[off + 32 + lane];
        }
#pragma unroll 8
        for (int k = 0; k < 32; k++) {
            float2 wlk = *(const float2*)(wl + k * 64 + c);
            float2 wrk = *(const float2*)(wr + k * 64 + c);
#pragma unroll
            for (int i = 0; i < 4; i++) {
                float ak = __shfl_sync(0xffffffffu, a_lo[i], k);
                float hk = __shfl_sync(0xffffffffu, h_lo[i], k);
                acc[i].x += ak * wlk.x + hk * wrk.x;
                acc[i].y += ak * wlk.y + hk * wrk.y;
            }
        }
#pragma unroll 8
        for (int k = 0; k < 32; k++) {
            float2 wlk = *(const float2*)(wl + (k + 32) * 64 + c);
            float2 wrk = *(const float2*)(wr + (k + 32) * 64 + c);
#pragma unroll
            for (int i = 0; i < 4; i++) {
                float ak = __shfl_sync(0xffffffffu, a_hi[i], k);
                float hk = __shfl_sync(0xffffffffu, h_hi[i], k);
                acc[i].x += ak * wlk.x + hk * wrk.x;
                acc[i].y += ak * wlk.y + hk * wrk.y;
            }
        }
#pragma unroll
        for (int i = 0; i < 4; i++)
            *(float2*)(out + (size_t)(base + li0 + i) * 64 + c) = acc[i];
    } else {
        // ---- fallback: per node ----
        for (int i = 0; i < 4; i++) {
            size_t off = (size_t)(base + li0 + i) * 64;
            if (n[i] == 0) {
                if (copy) {
                    float2 v = *(const float2*)(in_dst + off + lane * 2);
                    *(float2*)(out + off + lane * 2) = v;
                }
                continue;
            }
            conv_one(in_src, in_dst, out, ep[i], n[i], lane, off, Wl, bl, Wr);
        }
    }
}

// ---------------- pool over ground nodes (scalar f32 atomics) ----------------
__global__ void pool_kernel(const int* __restrict__ batch_idx, const float* __restrict__ buf) {
    int gid = blockIdx.x * blockDim.x + threadIdx.x;  // NG*64
    int i  = gid >> 6;
    int cc = gid & 63;
    int b = __ldg(batch_idx + i);
    atomicAdd(&g_pooled[b * 64 + cc], buf[(size_t)i * 64 + cc]);
}

// ---------------- head: out = relu(pooled@W1+b1) @ W2 + b2 ----------------
__global__ void head_kernel(const float* __restrict__ W1, const float* __restrict__ b1,
                            const float* __restrict__ W2, const float* __restrict__ b2,
                            float* __restrict__ out) {
    int bidx = blockIdx.x;
    int c = threadIdx.x;
    float acc = b1[c];
#pragma unroll 8
    for (int k = 0; k < 64; k++)
        acc += g_pooled[bidx * 64 + k] * W1[k * 64 + c];
    acc = fmaxf(acc, 0.f) * W2[c];
#pragma unroll
    for (int o = 16; o > 0; o >>= 1)
        acc += __shfl_down_sync(0xffffffffu, acc, o);
    __shared__ float s[2];
    if ((threadIdx.x & 31) == 0) s[threadIdx.x >> 5] = acc;
    __syncthreads();
    if (threadIdx.x == 0) out[bidx] = s[0] + s[1] + b2[0];
}

extern "C" void kernel_launch(void* const* d_in, const int* in_sizes, int n_in,
                              void* d_out, int out_size) {
    const float* x          = (const float*)d_in[0];
    const int*   edge_index = (const int*)d_in[1];   // JAX x64-disabled -> int32
    const int*   sub_ei     = (const int*)d_in[2];
    const int*   ns_ei      = (const int*)d_in[3];
    const int*   sn_ei      = (const int*)d_in[4];
    const int*   batch_idx  = (const int*)d_in[7];
    const float* embed_W = (const float*)d_in[8];
    const float* embed_b = (const float*)d_in[9];
    const float* Wl[4] = {(const float*)d_in[10], (const float*)d_in[13],
                          (const float*)d_in[16], (const float*)d_in[19]};
    const float* bl[4] = {(const float*)d_in[11], (const float*)d_in[14],
                          (const float*)d_in[17], (const float*)d_in[20]};
    const float* Wr[4] = {(const float*)d_in[12], (const float*)d_in[15],
                          (const float*)d_in[18], (const float*)d_in[21]};
    const float* W1 = (const float*)d_in[22];
    const float* b1 = (const float*)d_in[23];
    const float* W2 = (const float*)d_in[24];
    const float* b2 = (const float*)d_in[25];
    float* out = (float*)d_out;

    int E0 = in_sizes[1] / 2;   // ground   (t=0)
    int E1 = in_sizes[3] / 2;   // g2s      (t=1)
    int E2 = in_sizes[2] / 2;   // sub      (t=2)
    int E3 = in_sizes[4] / 2;   // s2g      (t=3)

    float* bufs[2]; 
    cudaGetSymbolAddress((void**)&bufs[0], g_h);
    cudaGetSymbolAddress((void**)&bufs[1], g_h2);

    zero_kernel<<<(4 * NGR + BB * HH + 255) / 256, 256>>>();
    embed_kernel<<<NN / 8, 256>>>(x, embed_W, embed_b);
    fill_all_kernel<<<(E0 + E1 + E2 + E3 + 255) / 256, 256>>>(
        edge_index, ns_ei, sub_ei, sn_ei, E0, E1, E2, E3);

    int fg = 0, fs = 0;   // which buffer holds the current ground / sub half
    int bases[4] = {0, NGR, NGR, 0};
    for (int l = 0; l < 2; l++) {
        if (l) relu2_kernel<<<(NN * 16) / 256, 256>>>(bufs[fg], bufs[fs]);
        for (int t = 0; t < 4; t++) {
            size_t woff = (size_t)l * (MAXD + 1) * 64 * 64;
            size_t boff = (size_t)l * (MAXD + 1) * 64;
            const float* src; const float* dst; float* o; int copy;
            if (t == 0)      { src = bufs[fg]; dst = bufs[fg]; o = bufs[1 - fg]; copy = 1; }
            else if (t == 1) { src = bufs[fg]; dst = bufs[fs]; o = bufs[fs];     copy = 0; }
            else if (t == 2) { src = bufs[fs]; dst = bufs[fs]; o = bufs[1 - fs]; copy = 1; }
            else             { src = bufs[fs]; dst = bufs[fg]; o = bufs[fg];     copy = 0; }
            conv_kernel<<<NGR / 32, 256>>>(src, dst, o, t, bases[t], copy,
                                           Wl[t] + woff, bl[t] + boff, Wr[t] + woff);
            if (t == 0) fg ^= 1;
            if (t == 2) fs ^= 1;
        }
    }

    pool_kernel<<<(NGR * 64) / 256, 256>>>(batch_idx, bufs[fg]);
    head_kernel<<<BB, 64>>>(W1, b1, W2, b2, out);
}

// round 12
// speedup vs baseline: 1.7728x; 1.0919x over previous
#include <cuda_runtime.h>
#include <cuda_bf16.h>

#define NN    65536
#define NGR   32768
#define HH    64
#define BB    64
#define MAXD  10
#define BKT   128      // bucket capacity per (type,node); max real degree ~70
#define ZR    NN       // zero-row node id (padding target)

// ---- scratch: device globals (no allocation allowed) ----
__device__ __align__(16) float g_h [(size_t)(NN + 1) * HH];   // ping (+ zero row)
__device__ __align__(16) float g_h2[(size_t)(NN + 1) * HH];   // pong (+ zero row)
__device__ __align__(16) int   g_bkt[(size_t)4 * NGR * BKT];  // 64MB dst-bucketed src ids
__device__ int   g_cnt[4][NGR];                               // per-conv-type receive degree
__device__ float g_pooled[BB * HH];

// ---------------- init: pad buckets with ZR, zero counters/pooled/zero-rows ----------------
__global__ void init_kernel() {
    int gid = blockIdx.x * blockDim.x + threadIdx.x;
    const int nbq = 4 * NGR * BKT / 4;
    if (gid < nbq) {
        ((int4*)g_bkt)[gid] = make_int4(ZR, ZR, ZR, ZR);
    } else {
        int r = gid - nbq;
        if (r < 4 * NGR) ((int*)g_cnt)[r] = 0;
        else if (r < 4 * NGR + BB * HH) g_pooled[r - 4 * NGR] = 0.f;
        else if (r < 4 * NGR + BB * HH + HH) {
            int z = r - 4 * NGR - BB * HH;
            g_h [(size_t)ZR * HH + z] = 0.f;
            g_h2[(size_t)ZR * HH + z] = 0.f;
        }
    }
}

// ---------------- single pass: bucket all 4 edge sets ----------------
__global__ void fill_all_kernel(const int* __restrict__ e0, const int* __restrict__ e1,
                                const int* __restrict__ e2, const int* __restrict__ e3,
                                int E0, int E1, int E2, int E3) {
    int e = blockIdx.x * blockDim.x + threadIdx.x;
    const int* ei; int E, t, base;
    if (e < E0)              { ei = e0; E = E0; t = 0; base = 0;   }
    else if ((e -= E0) < E1) { ei = e1; E = E1; t = 1; base = NGR; }
    else if ((e -= E1) < E2) { ei = e2; E = E2; t = 2; base = NGR; }
    else if ((e -= E2) < E3) { ei = e3; E = E3; t = 3; base = 0;   }
    else return;
    int src = __ldg(ei + e);
    int dst = __ldg(ei + E + e);
    int li  = dst - base;
    int slot = atomicAdd(&g_cnt[t][li], 1);
    if (slot < BKT) g_bkt[((size_t)(t * NGR + li) << 7) + slot] = src;
}

// ---------------- embed: h = x @ W(32x64) + b ----------------
__global__ void embed_kernel(const float* __restrict__ x,
                             const float* __restrict__ W,
                             const float* __restrict__ b) {
    int node = blockIdx.x * 8 + (threadIdx.x >> 5);
    int lane = threadIdx.x & 31;
    float xv = x[(size_t)node * 32 + lane];
    int c = lane * 2;
    float2 acc = make_float2(b[c], b[c + 1]);
#pragma unroll 8
    for (int k = 0; k < 32; k++) {
        float xk = __shfl_sync(0xffffffffu, xv, k);
        float2 w = *(const float2*)(W + k * 64 + c);
        acc.x += xk * w.x;
        acc.y += xk * w.y;
    }
    *(float2*)(g_h + (size_t)node * 64 + c) = acc;
}

// ---------------- relu on both current halves ----------------
__global__ void relu2_kernel(float* bg, float* bs) {
    int gid = blockIdx.x * blockDim.x + threadIdx.x;   // NN*16 quads
    float* buf = (gid < NGR * 16) ? bg : bs;           // halves at natural offsets
    float4* p = ((float4*)buf) + gid;
    float4 v = *p;
    v.x = fmaxf(v.x, 0.f); v.y = fmaxf(v.y, 0.f);
    v.z = fmaxf(v.z, 0.f); v.w = fmaxf(v.w, 0.f);
    *p = v;
}

// ---- single-node conv (fallback path; branch-free padded gather) ----
__device__ __forceinline__ void conv_one(const float* __restrict__ in_src,
                                         const float* __restrict__ in_dst,
                                         float* __restrict__ out,
                                         const int* __restrict__ ep, int n, int lane,
                                         size_t off,
                                         const float* __restrict__ Wl,
                                         const float* __restrict__ bl,
                                         const float* __restrict__ Wr) {
    float a_lo = 0.f, a_hi = 0.f;
    int nr = (n + 1) & ~1;              // padded slots read the zero row
    for (int e = 0; e < nr; e += 2) {
        int s0 = __ldg(ep + e), s1 = __ldg(ep + e + 1);
        a_lo += in_src[(size_t)s0 * 64 + lane] + in_src[(size_t)s1 * 64 + lane];
        a_hi += in_src[(size_t)s0 * 64 + 32 + lane] + in_src[(size_t)s1 * 64 + 32 + lane];
    }
    int d = n > MAXD ? MAXD : n;
    const float* wl = Wl + (size_t)d * 4096;
    const float* wr = Wr + (size_t)d * 4096;
    float h_lo = in_dst[off + lane];
    float h_hi = in_dst[off + 32 + lane];
    int c = lane * 2;
    float2 acc = *(const float2*)(bl + (size_t)d * 64 + c);
#pragma unroll 8
    for (int k = 0; k < 32; k++) {
        float ak = __shfl_sync(0xffffffffu, a_lo, k);
        float hk = __shfl_sync(0xffffffffu, h_lo, k);
        float2 wlk = *(const float2*)(wl + k * 64 + c);
        float2 wrk = *(const float2*)(wr + k * 64 + c);
        acc.x += ak * wlk.x + hk * wrk.x;
        acc.y += ak * wlk.y + hk * wrk.y;
    }
#pragma unroll 8
    for (int k = 0; k < 32; k++) {
        float ak = __shfl_sync(0xffffffffu, a_hi, k);
        float hk = __shfl_sync(0xffffffffu, h_hi, k);
        float2 wlk = *(const float2*)(wl + (k + 32) * 64 + c);
        float2 wrk = *(const float2*)(wr + (k + 32) * 64 + c);
        acc.x += ak * wlk.x + hk * wrk.x;
        acc.y += ak * wlk.y + hk * wrk.y;
    }
    *(float2*)(out + off + c) = acc;
}

// ---------------- fused conv: 4 nodes/warp, branch-free gather, shared weights ----------------
__global__ void conv_kernel(const float* __restrict__ in_src,
                            const float* __restrict__ in_dst,
                            float* __restrict__ out,
                            int t, int base, int copy,
                            const float* __restrict__ Wl,
                            const float* __restrict__ bl,
                            const float* __restrict__ Wr) {
    int warp = blockIdx.x * 8 + (threadIdx.x >> 5);
    int lane = threadIdx.x & 31;
    int li0 = warp * 4;                 // 4 consecutive local nodes
    int n[4], d[4];
    const int* ep[4];
    bool allpos = true;
#pragma unroll
    for (int i = 0; i < 4; i++) {
        int nn = g_cnt[t][li0 + i];
        if (nn > BKT) nn = BKT;
        n[i] = nn;
        d[i] = nn > MAXD ? MAXD : nn;
        ep[i] = g_bkt + ((size_t)(t * NGR + li0 + i) << 7);
        allpos &= (nn > 0);
    }
    if (allpos && d[0] == d[1] && d[0] == d[2] && d[0] == d[3]) {
        // ---- fast path: shared degree bucket, fully branch-free padded gather ----
        float a_lo[4] = {0, 0, 0, 0}, a_hi[4] = {0, 0, 0, 0};
        int nm = max(max(n[0], n[1]), max(n[2], n[3]));
        int nmr = (nm + 1) & ~1;
        for (int e = 0; e < nmr; e += 2) {
#pragma unroll
            for (int i = 0; i < 4; i++) {
                int s0 = __ldg(ep[i] + e);
                int s1 = __ldg(ep[i] + e + 1);
                a_lo[i] += in_src[(size_t)s0 * 64 + lane] + in_src[(size_t)s1 * 64 + lane];
                a_hi[i] += in_src[(size_t)s0 * 64 + 32 + lane] + in_src[(size_t)s1 * 64 + 32 + lane];
            }
        }
        int dd = d[0];
        const float* wl = Wl + (size_t)dd * 4096;
        const float* wr = Wr + (size_t)dd * 4096;
        int c = lane * 2;
        float2 bv = *(const float2*)(bl + (size_t)dd * 64 + c);
        float2 acc[4];
        float h_lo[4], h_hi[4];
#pragma unroll
        for (int i = 0; i < 4; i++) {
            acc[i] = bv;
            size_t off = (size_t)(base + li0 + i) * 64;
            h_lo[i] = in_dst[off + lane];
            h_hi[i] = in_dst[off + 32 + lane];
        }
#pragma unroll 8
        for (int k = 0; k < 32; k++) {
            float2 wlk = *(const float2*)(wl + k * 64 + c);
            float2 wrk = *(const float2*)(wr + k * 64 + c);
#pragma unroll
            for (int i = 0; i < 4; i++) {
                float ak = __shfl_sync(0xffffffffu, a_lo[i], k);
                float hk = __shfl_sync(0xffffffffu, h_lo[i], k);
                acc[i].x += ak * wlk.x + hk * wrk.x;
                acc[i].y += ak * wlk.y + hk * wrk.y;
            }
        }
#pragma unroll 8
        for (int k = 0; k < 32; k++) {
            float2 wlk = *(const float2*)(wl + (k + 32) * 64 + c);
            float2 wrk = *(const float2*)(wr + (k + 32) * 64 + c);
#pragma unroll
            for (int i = 0; i < 4; i++) {
                float ak = __shfl_sync(0xffffffffu, a_hi[i], k);
                float hk = __shfl_sync(0xffffffffu, h_hi[i], k);
                acc[i].x += ak * wlk.x + hk * wrk.x;
                acc[i].y += ak * wlk.y + hk * wrk.y;
            }
        }
#pragma unroll
        for (int i = 0; i < 4; i++)
            *(float2*)(out + (size_t)(base + li0 + i) * 64 + c) = acc[i];
    } else {
        // ---- fallback: per node ----
        for (int i = 0; i < 4; i++) {
            size_t off = (size_t)(base + li0 + i) * 64;
            if (n[i] == 0) {
                if (copy) {
                    float2 v = *(const float2*)(in_dst + off + lane * 2);
                    *(float2*)(out + off + lane * 2) = v;
                }
                continue;
            }
            conv_one(in_src, in_dst, out, ep[i], n[i], lane, off, Wl, bl, Wr);
        }
    }
}

// ---------------- pool over ground nodes (scalar f32 atomics) ----------------
__global__ void pool_kernel(const int* __restrict__ batch_idx, const float* __restrict__ buf) {
    int gid = blockIdx.x * blockDim.x + threadIdx.x;  // NG*64
    int i  = gid >> 6;
    int cc = gid & 63;
    int b = __ldg(batch_idx + i);
    atomicAdd(&g_pooled[b * 64 + cc], buf[(size_t)i * 64 + cc]);
}

// ---------------- head: out = relu(pooled@W1+b1) @ W2 + b2 ----------------
__global__ void head_kernel(const float* __restrict__ W1, const float* __restrict__ b1,
                            const float* __restrict__ W2, const float* __restrict__ b2,
                            float* __restrict__ out) {
    int bidx = blockIdx.x;
    int c = threadIdx.x;
    float acc = b1[c];
#pragma unroll 8
    for (int k = 0; k < 64; k++)
        acc += g_pooled[bidx * 64 + k] * W1[k * 64 + c];
    acc = fmaxf(acc, 0.f) * W2[c];
#pragma unroll
    for (int o = 16; o > 0; o >>= 1)
        acc += __shfl_down_sync(0xffffffffu, acc, o);
    __shared__ float s[2];
    if ((threadIdx.x & 31) == 0) s[threadIdx.x >> 5] = acc;
    __syncthreads();
    if (threadIdx.x == 0) out[bidx] = s[0] + s[1] + b2[0];
}

extern "C" void kernel_launch(void* const* d_in, const int* in_sizes, int n_in,
                              void* d_out, int out_size) {
    const float* x          = (const float*)d_in[0];
    const int*   edge_index = (const int*)d_in[1];   // JAX x64-disabled -> int32
    const int*   sub_ei     = (const int*)d_in[2];
    const int*   ns_ei      = (const int*)d_in[3];
    const int*   sn_ei      = (const int*)d_in[4];
    const int*   batch_idx  = (const int*)d_in[7];
    const float* embed_W = (const float*)d_in[8];
    const float* embed_b = (const float*)d_in[9];
    const float* Wl[4] = {(const float*)d_in[10], (const float*)d_in[13],
                          (const float*)d_in[16], (const float*)d_in[19]};
    const float* bl[4] = {(const float*)d_in[11], (const float*)d_in[14],
                          (const float*)d_in[17], (const float*)d_in[20]};
    const float* Wr[4] = {(const float*)d_in[12], (const float*)d_in[15],
                          (const float*)d_in[18], (const float*)d_in[21]};
    const float* W1 = (const float*)d_in[22];
    const float* b1 = (const float*)d_in[23];
    const float* W2 = (const float*)d_in[24];
    const float* b2 = (const float*)d_in[25];
    float* out = (float*)d_out;

    int E0 = in_sizes[1] / 2;   // ground   (t=0)
    int E1 = in_sizes[3] / 2;   // g2s      (t=1)
    int E2 = in_sizes[2] / 2;   // sub      (t=2)
    int E3 = in_sizes[4] / 2;   // s2g      (t=3)

    float* bufs[2];
    cudaGetSymbolAddress((void**)&bufs[0], g_h);
    cudaGetSymbolAddress((void**)&bufs[1], g_h2);

    const int initN = 4 * NGR * BKT / 4 + 4 * NGR + BB * HH + HH;
    init_kernel<<<(initN + 255) / 256, 256>>>();
    embed_kernel<<<NN / 8, 256>>>(x, embed_W, embed_b);
    fill_all_kernel<<<(E0 + E1 + E2 + E3 + 255) / 256, 256>>>(
        edge_index, ns_ei, sub_ei, sn_ei, E0, E1, E2, E3);

    int fg = 0, fs = 0;   // which buffer holds the current ground / sub half
    int bases[4] = {0, NGR, NGR, 0};
    for (int l = 0; l < 2; l++) {
        if (l) relu2_kernel<<<(NN * 16) / 256, 256>>>(bufs[fg], bufs[fs]);
        for (int t = 0; t < 4; t++) {
            size_t woff = (size_t)l * (MAXD + 1) * 64 * 64;
            size_t boff = (size_t)l * (MAXD + 1) * 64;
            const float* src; const float* dst; float* o; int copy;
            if (t == 0)      { src = bufs[fg]; dst = bufs[fg]; o = bufs[1 - fg]; copy = 1; }
            else if (t == 1) { src = bufs[fg]; dst = bufs[fs]; o = bufs[fs];     copy = 0; }
            else if (t == 2) { src = bufs[fs]; dst = bufs[fs]; o = bufs[1 - fs]; copy = 1; }
            else             { src = bufs[fs]; dst = bufs[fg]; o = bufs[fg];     copy = 0; }
            conv_kernel<<<NGR / 32, 256>>>(src, dst, o, t, bases[t], copy,
                                           Wl[t] + woff, bl[t] + boff, Wr[t] + woff);
            if (t == 0) fg ^= 1;
            if (t == 2) fs ^= 1;
        }
    }

    pool_kernel<<<(NGR * 64) / 256, 256>>>(batch_idx, bufs[fg]);
    head_kernel<<<BB, 64>>>(W1, b1, W2, b2, out);
}